// round 9
// baseline (speedup 1.0000x reference)
#include <cuda_runtime.h>

// ---------------------------------------------------------------------------
// PlainRNN: h_t = tanh(h_{t-1} @ W_eff + b_eff) with
//   W_eff = W_h2h + W_h2o @ W_i2h  (x feedback folded into the recurrence)
// 511 step-kernel launches (graph-captured). out[t] = h_t @ W_h2o + b_h2o
// is one big batched GEMM at the end.
//
// GEMM core: 32x64 CTA tile, BK=32, 256 threads.
// Warp = 8 rows x 32 cols sub-tile (thread = 2x4) -> per warp-kk only
// 4 broadcast A-words + 8 contiguous B-words on the smem crossbar;
// inner loop is FFMA2 (fma.rn.f32x2) issue-bound.
// ---------------------------------------------------------------------------

#define INPUT   128
#define HIDDEN  1024
#define OUTPUT  128
#define BATCH   256
#define TSTEPS  512

__device__ float g_H[TSTEPS][BATCH][HIDDEN];   // h_t for t=1..511
__device__ float g_Weff[HIDDEN * HIDDEN];
__device__ float g_beff[HIDDEN];
__device__ float g_b1[HIDDEN];

// ---------------- packed fp32x2 helpers ------------------------------------
__device__ __forceinline__ unsigned long long pack2(float lo, float hi) {
    unsigned long long r;
    asm("mov.b64 %0, {%1, %2};" : "=l"(r) : "f"(lo), "f"(hi));
    return r;
}
__device__ __forceinline__ void unpack2(unsigned long long v, float& lo, float& hi) {
    asm("mov.b64 {%0, %1}, %2;" : "=f"(lo), "=f"(hi) : "l"(v));
}
__device__ __forceinline__ void ffma2(unsigned long long& d,
                                      unsigned long long a,
                                      unsigned long long b) {
    asm("fma.rn.f32x2 %0, %1, %2, %0;" : "+l"(d) : "l"(a), "l"(b));
}

// ---------------------------------------------------------------------------
// One 32x64 output tile of C = act(A[.,K] @ B[K,.] + bias), BK=32,
// double-buffered smem, 256 threads. K % 32 == 0.
// ---------------------------------------------------------------------------
template <bool TANH>
__device__ __forceinline__ void gemm_tile(
    const float* __restrict__ A, int lda,
    const float* __restrict__ B, int ldb,
    const float* __restrict__ bias,
    float* __restrict__ C, int ldc,
    int K, int rowBase, int colBase)
{
    // Asd[k][m] = (A[m], A[m]) packed pair; row stride 34*8=272 (16B-aligned)
    __shared__ unsigned long long Asd[2][32][34];
    __shared__ float Bs[2][32][68];

    const int tid = threadIdx.x;
    const int w = tid >> 5, l = tid & 31;
    const int tr = ((w >> 1) << 3) + ((l >> 3) << 1);   // thread rows tr, tr+1
    const int tc = ((w & 1) << 5) + ((l & 7) << 2);     // thread cols tc..tc+3

    // stagers
    const int am = tid >> 3;            // 0..31 (row)
    const int ak = (tid & 7) << 2;      // 0,4,...,28 (k)
    const int bk = tid >> 4;            // 0..15 (k row, +16 for second)
    const int bn = (tid & 15) << 2;     // 0..60 (col)

    const float* Ap = A + (size_t)(rowBase + am) * lda + ak;
    const float* Bp = B + (size_t)bk * ldb + colBase + bn;

    unsigned long long acc[2][2];
    acc[0][0] = acc[0][1] = acc[1][0] = acc[1][1] = 0ull;

    float4 rA  = *(const float4*)Ap;
    float4 rB0 = *(const float4*)Bp;
    float4 rB1 = *(const float4*)(Bp + (size_t)16 * ldb);

    const int nT = K >> 5;
    for (int t = 0; t < nT; ++t) {
        const int buf = t & 1;
        Asd[buf][ak + 0][am] = pack2(rA.x, rA.x);
        Asd[buf][ak + 1][am] = pack2(rA.y, rA.y);
        Asd[buf][ak + 2][am] = pack2(rA.z, rA.z);
        Asd[buf][ak + 3][am] = pack2(rA.w, rA.w);
        *(float4*)&Bs[buf][bk][bn]      = rB0;
        *(float4*)&Bs[buf][bk + 16][bn] = rB1;
        __syncthreads();
        if (t + 1 < nT) {
            rA  = *(const float4*)(Ap + (t + 1) * 32);
            rB0 = *(const float4*)(Bp + (size_t)(t + 1) * 32 * ldb);
            rB1 = *(const float4*)(Bp + (size_t)((t + 1) * 32 + 16) * ldb);
        }
#pragma unroll
        for (int kk = 0; kk < 32; ++kk) {
            ulonglong2 ap = *(const ulonglong2*)&Asd[buf][kk][tr];
            ulonglong2 bp = *(const ulonglong2*)&Bs[buf][kk][tc];
            ffma2(acc[0][0], ap.x, bp.x);
            ffma2(acc[0][1], ap.x, bp.y);
            ffma2(acc[1][0], ap.y, bp.x);
            ffma2(acc[1][1], ap.y, bp.y);
        }
        // single sync per tile: writes(t+1) target buf^1 and happen after
        // sync(t); all reads of buf^1 (compute(t-1)) precede sync(t).
    }

    float4 bv = *(const float4*)&bias[colBase + tc];
    float o[2][4];
#pragma unroll
    for (int r = 0; r < 2; ++r) {
        unpack2(acc[r][0], o[r][0], o[r][1]);
        unpack2(acc[r][1], o[r][2], o[r][3]);
        o[r][0] += bv.x; o[r][1] += bv.y; o[r][2] += bv.z; o[r][3] += bv.w;
        if (TANH) {
#pragma unroll
            for (int c = 0; c < 4; ++c) o[r][c] = tanhf(o[r][c]);
        }
        float* cp = &C[(size_t)(rowBase + tr + r) * ldc + colBase + tc];
        *(float4*)cp = make_float4(o[r][0], o[r][1], o[r][2], o[r][3]);
    }
}

// ---------------------------- wrappers -------------------------------------

// h_1 = tanh(x_0 @ W_i2h + b_i2h + b_h2h)           grid (16, 8)
__global__ void __launch_bounds__(256, 1)
rnn_first(const float* __restrict__ x0, const float* __restrict__ Wi2h) {
    gemm_tile<true>(x0, INPUT, Wi2h, HIDDEN, g_b1,
                    &g_H[1][0][0], HIDDEN, INPUT,
                    blockIdx.y * 32, blockIdx.x * 64);
}

// h_t = tanh(h_{t-1} @ W_eff + b_eff)               grid (16, 8)
__global__ void __launch_bounds__(256, 1)
rnn_step(int t) {
    gemm_tile<true>(&g_H[t - 1][0][0], HIDDEN, g_Weff, HIDDEN, g_beff,
                    &g_H[t][0][0], HIDDEN, HIDDEN,
                    blockIdx.y * 32, blockIdx.x * 64);
}

// out[t] = h_t @ W_h2o + b_h2o for t=1..511         grid (2, 4088)
__global__ void __launch_bounds__(256, 1)
out_proj(const float* __restrict__ Wh2o, const float* __restrict__ bh2o,
         float* __restrict__ out) {
    gemm_tile<false>(&g_H[1][0][0], HIDDEN, Wh2o, OUTPUT, bh2o,
                     out + BATCH * OUTPUT, OUTPUT, HIDDEN,
                     blockIdx.y * 32, blockIdx.x * 64);
}

// ---------------------------- prep kernels ---------------------------------
__global__ void prep_weff(const float* __restrict__ Wh2h,
                          const float* __restrict__ Wh2o,
                          const float* __restrict__ Wi2h) {
    int idx = blockIdx.x * blockDim.x + threadIdx.x;
    int k = idx >> 10;
    int j = idx & 1023;
    float s = Wh2h[idx];
    const float* wo = &Wh2o[k * OUTPUT];
#pragma unroll 8
    for (int i = 0; i < OUTPUT; ++i)
        s += wo[i] * Wi2h[i * HIDDEN + j];
    g_Weff[idx] = s;
}

__global__ void prep_bias(const float* __restrict__ bi2h,
                          const float* __restrict__ bh2h,
                          const float* __restrict__ bh2o,
                          const float* __restrict__ Wi2h) {
    int j = blockIdx.x * blockDim.x + threadIdx.x;
    if (j >= HIDDEN) return;
    float base = bi2h[j] + bh2h[j];
    g_b1[j] = base;
    float s = base;
#pragma unroll 8
    for (int i = 0; i < OUTPUT; ++i)
        s += bh2o[i] * Wi2h[i * HIDDEN + j];
    g_beff[j] = s;
}

__global__ void copy_x0(const float* __restrict__ x0, float* __restrict__ out) {
    int i = blockIdx.x * blockDim.x + threadIdx.x;
    if (i < BATCH * OUTPUT) out[i] = x0[i];
}

// ---------------------------- launcher -------------------------------------
extern "C" void kernel_launch(void* const* d_in, const int* in_sizes, int n_in,
                              void* d_out, int out_size) {
    const float* x0   = (const float*)d_in[0];
    const float* Wi2h = (const float*)d_in[1];
    const float* bi2h = (const float*)d_in[2];
    const float* Wh2h = (const float*)d_in[3];
    const float* bh2h = (const float*)d_in[4];
    const float* Wh2o = (const float*)d_in[5];
    const float* bh2o = (const float*)d_in[6];
    float* out = (float*)d_out;

    prep_weff<<<(HIDDEN * HIDDEN) / 256, 256>>>(Wh2h, Wh2o, Wi2h);
    prep_bias<<<(HIDDEN + 255) / 256, 256>>>(bi2h, bh2h, bh2o, Wi2h);
    copy_x0<<<(BATCH * OUTPUT + 255) / 256, 256>>>(x0, out);

    const dim3 stepGrid(HIDDEN / 64, BATCH / 32);   // (16, 8) = 128 CTAs
    rnn_first<<<stepGrid, 256>>>(x0, Wi2h);
    for (int t = 2; t < TSTEPS; ++t)
        rnn_step<<<stepGrid, 256>>>(t);

    out_proj<<<dim3(OUTPUT / 64, ((TSTEPS - 1) * BATCH) / 32), 256>>>(Wh2o, bh2o, out);
}

// round 11
// speedup vs baseline: 3.3322x; 3.3322x over previous
#include <cuda_runtime.h>
#include <cuda_bf16.h>

#define INPUT   128
#define HIDDEN  1024
#define OUTPUT  128
#define BATCH   256
#define TSTEPS  512

// ---------------------------- device globals -------------------------------
__device__ float g_H[TSTEPS][BATCH][HIDDEN];            // h_t fp32, t=1..511
__device__ float g_beff[HIDDEN];
__device__ float g_b1[HIDDEN];
// bf16 split of h, double-buffered by step parity: [parity][hh=0/hl=1][m][k]
__device__ __nv_bfloat16 g_A[2][2][BATCH][HIDDEN];
// bf16 split of W_eff, transposed (n-major): [Wh=0/Wl=1][n][k]
__device__ __nv_bfloat16 g_BT[2][HIDDEN][HIDDEN];

// ---------------------------- PTX helpers ----------------------------------
__device__ __forceinline__ unsigned smem_u32(const void* p) {
    unsigned a;
    asm("{ .reg .u64 t; cvta.to.shared.u64 t, %1; cvt.u32.u64 %0, t; }"
        : "=r"(a) : "l"(p));
    return a;
}
__device__ __forceinline__ void cp16(unsigned s, const void* g) {
    asm volatile("cp.async.cg.shared.global [%0], [%1], 16;"
                 :: "r"(s), "l"(g) : "memory");
}
__device__ __forceinline__ void cp_commit() {
    asm volatile("cp.async.commit_group;" ::: "memory");
}
__device__ __forceinline__ void ldm4(unsigned* r, unsigned addr) {
    asm volatile("ldmatrix.sync.aligned.m8n8.x4.shared.b16 {%0,%1,%2,%3}, [%4];"
                 : "=r"(r[0]), "=r"(r[1]), "=r"(r[2]), "=r"(r[3]) : "r"(addr));
}
__device__ __forceinline__ void mma16816(float* d, const unsigned* a,
                                         const unsigned* b) {
    asm volatile(
        "mma.sync.aligned.m16n8k16.row.col.f32.bf16.bf16.f32 "
        "{%0,%1,%2,%3}, {%4,%5,%6,%7}, {%8,%9}, {%0,%1,%2,%3};"
        : "+f"(d[0]), "+f"(d[1]), "+f"(d[2]), "+f"(d[3])
        : "r"(a[0]), "r"(a[1]), "r"(a[2]), "r"(a[3]), "r"(b[0]), "r"(b[1]));
}

// ---------------------------------------------------------------------------
// HMMA recurrence step: h_t = tanh(h_{t-1} @ W_eff + b_eff)
//   = tanh( (hh+hl)@Wh + hh@Wl + b )   (hl@Wl dropped, ~2^-18)
// grid (16 ntile, 8 mtile) = 128 CTAs, 256 threads.
// CTA tile 32x64, warp tile 16x16 (warps 2m x 4n), K blocks of 16,
// 4-slot cp.async pipeline (3 in flight), one __syncthreads per block.
// smem rows padded to 24 bf16 (48B) -> conflict-free ldmatrix.
// ---------------------------------------------------------------------------
#define NKB   (HIDDEN / 16)      // 64 k16 blocks
#define APAD  24
#define A_STAGE_E (32 * APAD)    // elements per A stage
#define B_STAGE_E (64 * APAD)

__global__ void __launch_bounds__(256, 1) rnn_step_hmma(int t) {
    __shared__ __align__(16) __nv_bfloat16 sA[2][4][32][APAD];  // [hh/hl][slot]
    __shared__ __align__(16) __nv_bfloat16 sB[2][4][64][APAD];  // [Wh/Wl][slot]

    const int tid = threadIdx.x, wid = tid >> 5, l = tid & 31;
    const int nBase = blockIdx.x * 64, mBase = blockIdx.y * 32;
    const int rd = (t - 1) & 1, wr = t & 1;

    const __nv_bfloat16* gAh = &g_A[rd][0][mBase][0];
    const __nv_bfloat16* gAl = &g_A[rd][1][mBase][0];
    const __nv_bfloat16* gBh = &g_BT[0][nBase][0];
    const __nv_bfloat16* gBl = &g_BT[1][nBase][0];

    const unsigned baseA = smem_u32(&sA[0][0][0][0]);
    const unsigned baseB = smem_u32(&sB[0][0][0][0]);

    // ldmatrix lane offsets (bytes within one stage tile)
    const int rowA = ((wid >> 2) << 4) + (l & 15);
    const int colA = (l >> 4) << 3;
    const unsigned offA = (unsigned)(rowA * APAD + colA) * 2;
    const int rowB = ((wid & 3) << 4) + (l & 7) + ((l >> 4) << 3);
    const int colB = ((l >> 3) & 1) << 3;
    const unsigned offB = (unsigned)(rowB * APAD + colB) * 2;

    auto load_stage = [&](int slot, int kb) {
        const int k0 = kb * 16;
        for (int c = tid; c < 64; c += 256) {           // hh: 32 rows x 2
            int r = c >> 1, h = (c & 1) * 8;
            cp16(smem_u32(&sA[0][slot][r][h]), gAh + r * HIDDEN + k0 + h);
        }
        for (int c = tid; c < 64; c += 256) {           // hl
            int r = c >> 1, h = (c & 1) * 8;
            cp16(smem_u32(&sA[1][slot][r][h]), gAl + r * HIDDEN + k0 + h);
        }
        for (int c = tid; c < 128; c += 256) {          // Wh: 64 rows x 2
            int r = c >> 1, h = (c & 1) * 8;
            cp16(smem_u32(&sB[0][slot][r][h]), gBh + r * HIDDEN + k0 + h);
        }
        for (int c = tid; c < 128; c += 256) {          // Wl
            int r = c >> 1, h = (c & 1) * 8;
            cp16(smem_u32(&sB[1][slot][r][h]), gBl + r * HIDDEN + k0 + h);
        }
    };

    float acc0[4] = {0.f, 0.f, 0.f, 0.f};
    float acc1[4] = {0.f, 0.f, 0.f, 0.f};

    load_stage(0, 0); cp_commit();
    load_stage(1, 1); cp_commit();
    load_stage(2, 2); cp_commit();

    for (int kb = 0; kb < NKB; ++kb) {
        asm volatile("cp.async.wait_group 2;" ::: "memory");
        __syncthreads();                         // stage kb ready; slot kb-1 free
        if (kb + 3 < NKB) load_stage((kb + 3) & 3, kb + 3);
        cp_commit();                             // uniform group accounting

        const int slot = kb & 3;
        const unsigned aHH = baseA + (unsigned)(slot * A_STAGE_E) * 2 + offA;
        const unsigned aHL = aHH + (unsigned)(4 * A_STAGE_E) * 2;
        const unsigned bWH = baseB + (unsigned)(slot * B_STAGE_E) * 2 + offB;
        const unsigned bWL = bWH + (unsigned)(4 * B_STAGE_E) * 2;

        unsigned Ah[4], Al[4], Bh[4], Bl[4];
        ldm4(Ah, aHH);
        ldm4(Al, aHL);
        ldm4(Bh, bWH);
        ldm4(Bl, bWL);

        mma16816(acc0, Ah, Bh);       // hh @ Wh   (n8 tile 0)
        mma16816(acc1, Ah, Bh + 2);   //           (n8 tile 1)
        mma16816(acc0, Al, Bh);       // hl @ Wh
        mma16816(acc1, Al, Bh + 2);
        mma16816(acc0, Ah, Bl);       // hh @ Wl
        mma16816(acc1, Ah, Bl + 2);
    }
    asm volatile("cp.async.wait_group 0;" ::: "memory");

    // epilogue: bias + tanh; write fp32 h and next-step bf16 split planes
    const int g = l >> 2, tq = l & 3;
    const int m0 = mBase + ((wid >> 2) << 4);
    const int n0 = nBase + ((wid & 3) << 4);
#pragma unroll
    for (int half = 0; half < 2; ++half) {
        const int m = m0 + g + half * 8;
#pragma unroll
        for (int j = 0; j < 2; ++j) {
            const float* acc = j ? acc1 : acc0;
            const int n = n0 + j * 8 + 2 * tq;
            float v0 = tanhf(acc[2 * half]     + g_beff[n]);
            float v1 = tanhf(acc[2 * half + 1] + g_beff[n + 1]);
            *(float2*)&g_H[t][m][n] = make_float2(v0, v1);
            __nv_bfloat16 h0 = __float2bfloat16(v0);
            __nv_bfloat16 h1 = __float2bfloat16(v1);
            __nv_bfloat162 hh; hh.x = h0; hh.y = h1;
            __nv_bfloat162 hl;
            hl.x = __float2bfloat16(v0 - __bfloat162float(h0));
            hl.y = __float2bfloat16(v1 - __bfloat162float(h1));
            *(__nv_bfloat162*)&g_A[wr][0][m][n] = hh;
            *(__nv_bfloat162*)&g_A[wr][1][m][n] = hl;
        }
    }
}

// ---------------------------------------------------------------------------
// fp32 FFMA2 GEMM core (proven R4) for rnn_first / out_proj.
// ---------------------------------------------------------------------------
__device__ __forceinline__ unsigned long long pack2(float lo, float hi) {
    unsigned long long r;
    asm("mov.b64 %0, {%1, %2};" : "=l"(r) : "f"(lo), "f"(hi));
    return r;
}
__device__ __forceinline__ void unpack2(unsigned long long v, float& lo, float& hi) {
    asm("mov.b64 {%0, %1}, %2;" : "=f"(lo), "=f"(hi) : "l"(v));
}
__device__ __forceinline__ void ffma2(unsigned long long& d,
                                      unsigned long long a, unsigned long long b) {
    asm("fma.rn.f32x2 %0, %1, %2, %0;" : "+l"(d) : "l"(a), "l"(b));
}

template <bool TANH>
__device__ __forceinline__ void gemm2(
    const float* __restrict__ A, int lda,
    const float* __restrict__ B, int ldb,
    const float* __restrict__ bias,
    float* __restrict__ C, int ldc, int K)
{
    __shared__ unsigned long long Asd[2][16][34];
    __shared__ float Bs[2][16][68];

    const int tid = threadIdx.x;
    const int tx = tid & 15, ty = tid >> 4;
    const int rowBase = blockIdx.y * 32;
    const int colBase = blockIdx.x * 64;
    const int am = tid >> 3, ak = (tid & 7) * 2;
    const int bk = tid >> 4, bn = (tid & 15) * 4;

    const float* Aptr = &A[(size_t)(rowBase + am) * lda + ak];
    const float* Bptr = &B[(size_t)bk * ldb + colBase + bn];

    unsigned long long acc[2][2];
    acc[0][0] = acc[0][1] = acc[1][0] = acc[1][1] = 0ull;

    float2 rA = *(const float2*)Aptr;
    float4 rB = *(const float4*)Bptr;

    const int nT = K >> 4;
    for (int tt = 0; tt < nT; ++tt) {
        const int buf = tt & 1;
        Asd[buf][ak][am]     = pack2(rA.x, rA.x);
        Asd[buf][ak + 1][am] = pack2(rA.y, rA.y);
        *(float4*)&Bs[buf][bk][bn] = rB;
        __syncthreads();
        if (tt + 1 < nT) {
            rA = *(const float2*)(Aptr + (tt + 1) * 16);
            rB = *(const float4*)(Bptr + (size_t)(tt + 1) * 16 * ldb);
        }
#pragma unroll
        for (int kk = 0; kk < 16; ++kk) {
            ulonglong2 ap = *(const ulonglong2*)&Asd[buf][kk][2 * ty];
            ulonglong2 bp = *(const ulonglong2*)&Bs[buf][kk][4 * tx];
            ffma2(acc[0][0], ap.x, bp.x);
            ffma2(acc[0][1], ap.x, bp.y);
            ffma2(acc[1][0], ap.y, bp.x);
            ffma2(acc[1][1], ap.y, bp.y);
        }
    }

    float4 bv = *(const float4*)&bias[colBase + 4 * tx];
    float o[2][4];
#pragma unroll
    for (int r = 0; r < 2; ++r) {
        unpack2(acc[r][0], o[r][0], o[r][1]);
        unpack2(acc[r][1], o[r][2], o[r][3]);
        o[r][0] += bv.x; o[r][1] += bv.y; o[r][2] += bv.z; o[r][3] += bv.w;
        if (TANH) {
#pragma unroll
            for (int c = 0; c < 4; ++c) o[r][c] = tanhf(o[r][c]);
        }
        float* cp = &C[(size_t)(rowBase + 2 * ty + r) * ldc + colBase + 4 * tx];
        *(float4*)cp = make_float4(o[r][0], o[r][1], o[r][2], o[r][3]);
    }
}

__global__ void rnn_first(const float* __restrict__ x0,
                          const float* __restrict__ Wi2h) {
    gemm2<true>(x0, INPUT, Wi2h, HIDDEN, g_b1, &g_H[1][0][0], HIDDEN, INPUT);
}

__global__ void out_proj(const float* __restrict__ Wh2o,
                         const float* __restrict__ bh2o,
                         float* __restrict__ out) {
    gemm2<false>(&g_H[1][0][0], HIDDEN, Wh2o, OUTPUT, bh2o,
                 out + BATCH * OUTPUT, OUTPUT, HIDDEN);
}

// ---------------------------- prep kernels ---------------------------------
// W_eff[k][j] = W_h2h[k][j] + sum_i W_h2o[k][i]*W_i2h[i][j];
// store transposed bf16 split planes g_BT[0/1][j][k].
__global__ void prep_weff(const float* __restrict__ Wh2h,
                          const float* __restrict__ Wh2o,
                          const float* __restrict__ Wi2h) {
    int idx = blockIdx.x * blockDim.x + threadIdx.x;
    int k = idx >> 10, j = idx & 1023;
    float s = Wh2h[idx];
    const float* wo = &Wh2o[k * OUTPUT];
#pragma unroll 8
    for (int i = 0; i < OUTPUT; ++i)
        s += wo[i] * Wi2h[i * HIDDEN + j];
    __nv_bfloat16 wh = __float2bfloat16(s);
    g_BT[0][j][k] = wh;
    g_BT[1][j][k] = __float2bfloat16(s - __bfloat162float(wh));
}

__global__ void prep_bias(const float* __restrict__ bi2h,
                          const float* __restrict__ bh2h,
                          const float* __restrict__ bh2o,
                          const float* __restrict__ Wi2h) {
    int j = blockIdx.x * blockDim.x + threadIdx.x;
    if (j >= HIDDEN) return;
    float base = bi2h[j] + bh2h[j];
    g_b1[j] = base;
    float s = base;
#pragma unroll 8
    for (int i = 0; i < OUTPUT; ++i)
        s += bh2o[i] * Wi2h[i * HIDDEN + j];
    g_beff[j] = s;
}

// split h_1 into bf16 planes at parity 1 (read by step t=2)
__global__ void split_h1() {
    int idx = blockIdx.x * blockDim.x + threadIdx.x;   // 256*1024
    int m = idx >> 10, n = idx & 1023;
    float x = g_H[1][m][n];
    __nv_bfloat16 h = __float2bfloat16(x);
    g_A[1][0][m][n] = h;
    g_A[1][1][m][n] = __float2bfloat16(x - __bfloat162float(h));
}

__global__ void copy_x0(const float* __restrict__ x0, float* __restrict__ out) {
    int i = blockIdx.x * blockDim.x + threadIdx.x;
    if (i < BATCH * OUTPUT) out[i] = x0[i];
}

// ---------------------------- launcher -------------------------------------
extern "C" void kernel_launch(void* const* d_in, const int* in_sizes, int n_in,
                              void* d_out, int out_size) {
    const float* x0   = (const float*)d_in[0];
    const float* Wi2h = (const float*)d_in[1];
    const float* bi2h = (const float*)d_in[2];
    const float* Wh2h = (const float*)d_in[3];
    const float* bh2h = (const float*)d_in[4];
    const float* Wh2o = (const float*)d_in[5];
    const float* bh2o = (const float*)d_in[6];
    float* out = (float*)d_out;

    prep_weff<<<(HIDDEN * HIDDEN) / 256, 256>>>(Wh2h, Wh2o, Wi2h);
    prep_bias<<<(HIDDEN + 255) / 256, 256>>>(bi2h, bh2h, bh2o, Wi2h);
    copy_x0<<<(BATCH * OUTPUT + 255) / 256, 256>>>(x0, out);

    rnn_first<<<dim3(HIDDEN / 64, BATCH / 32), 256>>>(x0, Wi2h);
    split_h1<<<(BATCH * HIDDEN) / 256, 256>>>();

    for (int t = 2; t < TSTEPS; ++t)
        rnn_step_hmma<<<dim3(16, 8), 256>>>(t);

    out_proj<<<dim3(OUTPUT / 64, ((TSTEPS - 1) * BATCH) / 32), 256>>>(Wh2o, bh2o, out);
}

// round 12
// speedup vs baseline: 4.9581x; 1.4879x over previous
#include <cuda_runtime.h>
#include <cuda_bf16.h>

#define INPUT   128
#define HIDDEN  1024
#define OUTPUT  128
#define BATCH   256
#define TSTEPS  512

// ---------------------------- device globals -------------------------------
__device__ float g_H1[BATCH][HIDDEN];                   // h_1 fp32 (from rnn_first)
__device__ float g_beff[HIDDEN];
__device__ float g_b1[HIDDEN];
// bf16 split planes of h_t for every t: [t][hh=0/hl=1][m][k]
__device__ __align__(16) __nv_bfloat16 g_Hs[TSTEPS][2][BATCH][HIDDEN];
// bf16 split of W_eff, transposed (n-major): [Wh=0/Wl=1][n][k]
__device__ __align__(16) __nv_bfloat16 g_BT[2][HIDDEN][HIDDEN];
// bf16 split of W_h2o, transposed (n-major): [Wh=0/Wl=1][n][k]
__device__ __align__(16) __nv_bfloat16 g_BTo[2][OUTPUT][HIDDEN];

// ---------------------------- PTX helpers ----------------------------------
__device__ __forceinline__ unsigned smem_u32(const void* p) {
    unsigned a;
    asm("{ .reg .u64 t; cvta.to.shared.u64 t, %1; cvt.u32.u64 %0, t; }"
        : "=r"(a) : "l"(p));
    return a;
}
__device__ __forceinline__ void cp16(unsigned s, const void* g) {
    asm volatile("cp.async.cg.shared.global [%0], [%1], 16;"
                 :: "r"(s), "l"(g) : "memory");
}
__device__ __forceinline__ void cp_commit() {
    asm volatile("cp.async.commit_group;" ::: "memory");
}
__device__ __forceinline__ void ldm4(unsigned* r, unsigned addr) {
    asm volatile("ldmatrix.sync.aligned.m8n8.x4.shared.b16 {%0,%1,%2,%3}, [%4];"
                 : "=r"(r[0]), "=r"(r[1]), "=r"(r[2]), "=r"(r[3]) : "r"(addr));
}
__device__ __forceinline__ void mma16816(float* d, const unsigned* a,
                                         const unsigned* b) {
    asm volatile(
        "mma.sync.aligned.m16n8k16.row.col.f32.bf16.bf16.f32 "
        "{%0,%1,%2,%3}, {%4,%5,%6,%7}, {%8,%9}, {%0,%1,%2,%3};"
        : "+f"(d[0]), "+f"(d[1]), "+f"(d[2]), "+f"(d[3])
        : "r"(a[0]), "r"(a[1]), "r"(a[2]), "r"(a[3]), "r"(b[0]), "r"(b[1]));
}

// ===========================================================================
// Step kernel: h_t = tanh(h_{t-1} @ W_eff + b_eff)
//   3-pass bf16 split: hh@Wh + hl@Wh + hh@Wl  (hl@Wl dropped, ~2^-18)
// grid (16 ntile, 8 mtile), 256 threads. CTA tile 32x64, warp tile 16x16.
// BK=32 stages (two k16 per stage), 4 slots, 3 in flight, one sync/stage.
// Dynamic smem 60KB: AH[4][32][40] AL BH[4][64][40] BL (bf16, 40-col pad).
// ===========================================================================
#define S_APAD   40
#define S_ASLOT  (32 * S_APAD)          // 1280 elems per A slot
#define S_BSLOT  (64 * S_APAD)          // 2560 elems per B slot
#define S_AH_OFF 0
#define S_AL_OFF (4 * S_ASLOT)          // 5120
#define S_BH_OFF (8 * S_ASLOT)          // 10240
#define S_BL_OFF (S_BH_OFF + 4 * S_BSLOT)   // 20480
#define S_TOTAL_E (S_BL_OFF + 4 * S_BSLOT)  // 30720 elems = 61440 B
#define S_NKB2   32                      // k32 blocks

__global__ void __launch_bounds__(256, 1) rnn_step_hmma(int t) {
    extern __shared__ __align__(16) __nv_bfloat16 dyn[];
    __nv_bfloat16* sAh = dyn + S_AH_OFF;
    __nv_bfloat16* sAl = dyn + S_AL_OFF;
    __nv_bfloat16* sBh = dyn + S_BH_OFF;
    __nv_bfloat16* sBl = dyn + S_BL_OFF;

    const int tid = threadIdx.x, wid = tid >> 5, l = tid & 31;
    const int nBase = blockIdx.x * 64, mBase = blockIdx.y * 32;

    const __nv_bfloat16* gAh = &g_Hs[t - 1][0][mBase][0];
    const __nv_bfloat16* gAl = &g_Hs[t - 1][1][mBase][0];
    const __nv_bfloat16* gBh = &g_BT[0][nBase][0];
    const __nv_bfloat16* gBl = &g_BT[1][nBase][0];

    // loader indices
    const int a_part = tid >> 7;               // 0/1
    const int a_r    = (tid & 127) >> 2;       // 0..31
    const int a_s    = (tid & 3) * 8;          // seg*8 elems
    __nv_bfloat16* a_dst0 = (a_part ? sAl : sAh) + a_r * S_APAD + a_s;
    const __nv_bfloat16* a_src0 = (a_part ? gAl : gAh) + a_r * HIDDEN + a_s;

    // B: 512 cp16 -> 2 per thread
    const int b0_part = 0, b1_part = 1;        // c = tid (0..255): part 0; c+256: part 1
    const int b_r = tid >> 2;                  // 0..63
    const int b_s = (tid & 3) * 8;
    __nv_bfloat16* b_dst0 = sBh + b_r * S_APAD + b_s;
    __nv_bfloat16* b_dst1 = sBl + b_r * S_APAD + b_s;
    const __nv_bfloat16* b_src0 = gBh + b_r * HIDDEN + b_s;
    const __nv_bfloat16* b_src1 = gBl + b_r * HIDDEN + b_s;

    auto load_stage = [&](int slot, int kb) {
        const int k0 = kb * 32;
        cp16(smem_u32(a_dst0 + slot * S_ASLOT), a_src0 + k0);
        cp16(smem_u32(b_dst0 + slot * S_BSLOT), b_src0 + k0);
        cp16(smem_u32(b_dst1 + slot * S_BSLOT), b_src1 + k0);
    };

    // ldmatrix lane offsets (bytes within a slot)
    const int rowA = ((wid >> 2) << 4) + (l & 15);
    const unsigned offA = (unsigned)(rowA * S_APAD + ((l >> 4) << 3)) * 2;
    const int rowB = ((wid & 3) << 4) + (l & 7) + ((l >> 4) << 3);
    const unsigned offB = (unsigned)(rowB * S_APAD + (((l >> 3) & 1) << 3)) * 2;

    const unsigned uAh = smem_u32(sAh) + offA;
    const unsigned uAl = smem_u32(sAl) + offA;
    const unsigned uBh = smem_u32(sBh) + offB;
    const unsigned uBl = smem_u32(sBl) + offB;

    float acc0[4] = {0.f, 0.f, 0.f, 0.f};
    float acc1[4] = {0.f, 0.f, 0.f, 0.f};

    load_stage(0, 0); cp_commit();
    load_stage(1, 1); cp_commit();
    load_stage(2, 2); cp_commit();

    for (int kb = 0; kb < S_NKB2; ++kb) {
        asm volatile("cp.async.wait_group 2;" ::: "memory");
        __syncthreads();
        if (kb + 3 < S_NKB2) load_stage((kb + 3) & 3, kb + 3);
        cp_commit();

        const int slot = kb & 3;
        const unsigned aH = uAh + (unsigned)(slot * S_ASLOT) * 2;
        const unsigned aL = uAl + (unsigned)(slot * S_ASLOT) * 2;
        const unsigned bH = uBh + (unsigned)(slot * S_BSLOT) * 2;
        const unsigned bL = uBl + (unsigned)(slot * S_BSLOT) * 2;

#pragma unroll
        for (int kj = 0; kj < 2; ++kj) {
            unsigned Ah[4], Al[4], Bh[4], Bl[4];
            ldm4(Ah, aH + kj * 32);
            ldm4(Al, aL + kj * 32);
            ldm4(Bh, bH + kj * 32);
            ldm4(Bl, bL + kj * 32);
            mma16816(acc0, Ah, Bh);
            mma16816(acc1, Ah, Bh + 2);
            mma16816(acc0, Al, Bh);
            mma16816(acc1, Al, Bh + 2);
            mma16816(acc0, Ah, Bl);
            mma16816(acc1, Ah, Bl + 2);
        }
    }
    asm volatile("cp.async.wait_group 0;" ::: "memory");

    // epilogue: bias + tanh; write bf16 split planes for step t (+out_proj)
    const int g = l >> 2, tq = l & 3;
    const int m0 = mBase + ((wid >> 2) << 4);
    const int n0 = nBase + ((wid & 3) << 4);
#pragma unroll
    for (int half = 0; half < 2; ++half) {
        const int m = m0 + g + half * 8;
#pragma unroll
        for (int j = 0; j < 2; ++j) {
            const float* acc = j ? acc1 : acc0;
            const int n = n0 + j * 8 + 2 * tq;
            float v0 = tanhf(acc[2 * half]     + g_beff[n]);
            float v1 = tanhf(acc[2 * half + 1] + g_beff[n + 1]);
            __nv_bfloat16 h0 = __float2bfloat16(v0);
            __nv_bfloat16 h1 = __float2bfloat16(v1);
            __nv_bfloat162 hh; hh.x = h0; hh.y = h1;
            __nv_bfloat162 hl;
            hl.x = __float2bfloat16(v0 - __bfloat162float(h0));
            hl.y = __float2bfloat16(v1 - __bfloat162float(h1));
            *(__nv_bfloat162*)&g_Hs[t][0][m][n] = hh;
            *(__nv_bfloat162*)&g_Hs[t][1][m][n] = hl;
        }
    }
}

// ===========================================================================
// out_proj on HMMA: out[t] = h_t @ W_h2o + b_h2o for t=1..511.
// C rows r = (t-1)*256 + m, 130816 rows. CTA tile 128x64 (warps 4m x 2n,
// warp tile 32x32). BK=16, 4 slots, 3 in flight. Dynamic smem 72KB.
// ===========================================================================
#define O_APAD   24
#define O_ASLOT  (128 * O_APAD)         // 3072 elems
#define O_BSLOT  (64 * O_APAD)          // 1536 elems
#define O_AH_OFF 0
#define O_AL_OFF (4 * O_ASLOT)
#define O_BH_OFF (8 * O_ASLOT)
#define O_BL_OFF (O_BH_OFF + 4 * O_BSLOT)
#define O_TOTAL_E (O_BL_OFF + 4 * O_BSLOT)   // 36864 elems = 73728 B
#define O_NKB    64

__global__ void __launch_bounds__(256, 1)
out_proj_hmma(const float* __restrict__ bh2o, float* __restrict__ out) {
    extern __shared__ __align__(16) __nv_bfloat16 dyn[];
    __nv_bfloat16* sAh = dyn + O_AH_OFF;
    __nv_bfloat16* sAl = dyn + O_AL_OFF;
    __nv_bfloat16* sBh = dyn + O_BH_OFF;
    __nv_bfloat16* sBl = dyn + O_BL_OFF;

    const int tid = threadIdx.x, wid = tid >> 5, l = tid & 31;
    const int nBase = blockIdx.x * 64;
    const int rBase = blockIdx.y * 128;           // global C row base
    const int t = rBase / 256 + 1;                // 128 | 256 -> single t per CTA
    const int mloc = rBase & 255;

    const __nv_bfloat16* gAh = &g_Hs[t][0][mloc][0];
    const __nv_bfloat16* gAl = &g_Hs[t][1][mloc][0];
    const __nv_bfloat16* gBh = &g_BTo[0][nBase][0];
    const __nv_bfloat16* gBl = &g_BTo[1][nBase][0];

    // A: 2 parts x 128 rows x 2 segs = 512 cp16 -> 2/thread
    const int a_part = tid >> 7;
    const int a_r0   = (tid & 127);               // handles segs 0 and 1 rows? no:
    // c = tid: rows 0..63 seg pairs -> use: r = (tid&127)>>1? Simpler mapping:
    // c in [0,512): part = c>>8, r = (c&255)>>1, s = (c&1)*8
    auto load_stage = [&](int slot, int kb) {
        const int k0 = kb * 16;
#pragma unroll
        for (int i = 0; i < 2; ++i) {
            int c = tid + i * 256;
            int part = c >> 8, r = (c & 255) >> 1, s = (c & 1) * 8;
            __nv_bfloat16* d = (part ? sAl : sAh) + slot * O_ASLOT + r * O_APAD + s;
            const __nv_bfloat16* src = (part ? gAl : gAh) + r * HIDDEN + k0 + s;
            cp16(smem_u32(d), src);
        }
        {   // B: 2 parts x 64 rows x 2 segs = 256 -> 1/thread
            int c = tid;
            int part = c >> 7, r = (c & 127) >> 1, s = (c & 1) * 8;
            __nv_bfloat16* d = (part ? sBl : sBh) + slot * O_BSLOT + r * O_APAD + s;
            const __nv_bfloat16* src = (part ? gBl : gBh) + r * HIDDEN + k0 + s;
            cp16(smem_u32(d), src);
        }
    };

    const int warpM = (wid >> 1) << 5;            // 0,32,64,96
    const int warpN = (wid & 1) << 5;             // 0,32
    const int rowA = warpM + (l & 15);
    const unsigned offA = (unsigned)(rowA * O_APAD + ((l >> 4) << 3)) * 2;
    const int rowB = warpN + (l & 7) + ((l >> 4) << 3);
    const unsigned offB = (unsigned)(rowB * O_APAD + (((l >> 3) & 1) << 3)) * 2;
    const unsigned mStride = (unsigned)(16 * O_APAD) * 2;  // +16 rows
    const unsigned uAh = smem_u32(sAh) + offA;
    const unsigned uAl = smem_u32(sAl) + offA;
    const unsigned uBh = smem_u32(sBh) + offB;
    const unsigned uBl = smem_u32(sBl) + offB;

    float acc[2][4][4];
#pragma unroll
    for (int a = 0; a < 2; ++a)
#pragma unroll
        for (int b = 0; b < 4; ++b)
#pragma unroll
            for (int c = 0; c < 4; ++c) acc[a][b][c] = 0.f;

    load_stage(0, 0); cp_commit();
    load_stage(1, 1); cp_commit();
    load_stage(2, 2); cp_commit();

    for (int kb = 0; kb < O_NKB; ++kb) {
        asm volatile("cp.async.wait_group 2;" ::: "memory");
        __syncthreads();
        if (kb + 3 < O_NKB) load_stage((kb + 3) & 3, kb + 3);
        cp_commit();

        const int slot = kb & 3;
        unsigned Ah[2][4], Al[2][4], Bh[8], Bl[8];
        ldm4(Ah[0], uAh + (unsigned)(slot * O_ASLOT) * 2);
        ldm4(Ah[1], uAh + (unsigned)(slot * O_ASLOT) * 2 + mStride);
        ldm4(Al[0], uAl + (unsigned)(slot * O_ASLOT) * 2);
        ldm4(Al[1], uAl + (unsigned)(slot * O_ASLOT) * 2 + mStride);
        ldm4(Bh,     uBh + (unsigned)(slot * O_BSLOT) * 2);
        ldm4(Bh + 4, uBh + (unsigned)(slot * O_BSLOT) * 2 + mStride);
        ldm4(Bl,     uBl + (unsigned)(slot * O_BSLOT) * 2);
        ldm4(Bl + 4, uBl + (unsigned)(slot * O_BSLOT) * 2 + mStride);

#pragma unroll
        for (int mi = 0; mi < 2; ++mi) {
#pragma unroll
            for (int nj = 0; nj < 4; ++nj) {
                mma16816(acc[mi][nj], Ah[mi], Bh + nj * 2);
                mma16816(acc[mi][nj], Al[mi], Bh + nj * 2);
                mma16816(acc[mi][nj], Ah[mi], Bl + nj * 2);
            }
        }
    }
    asm volatile("cp.async.wait_group 0;" ::: "memory");

    // epilogue: bias, fp32 store. out[0]=x0 occupies rows 0..255 -> offset.
    const int g = l >> 2, tq = l & 3;
    float* outBase = out + (size_t)(256 + rBase) * OUTPUT;
#pragma unroll
    for (int mi = 0; mi < 2; ++mi) {
#pragma unroll
        for (int nj = 0; nj < 4; ++nj) {
            const int n = nBase + warpN + nj * 8 + 2 * tq;
            const float b0 = bh2o[n], b1 = bh2o[n + 1];
#pragma unroll
            for (int half = 0; half < 2; ++half) {
                const int r = warpM + mi * 16 + g + half * 8;
                *(float2*)&outBase[(size_t)r * OUTPUT + n] =
                    make_float2(acc[mi][nj][2 * half] + b0,
                                acc[mi][nj][2 * half + 1] + b1);
            }
        }
    }
}

// ===========================================================================
// fp32 FFMA2 GEMM core (proven) for rnn_first only.
// ===========================================================================
__device__ __forceinline__ unsigned long long pack2(float lo, float hi) {
    unsigned long long r;
    asm("mov.b64 %0, {%1, %2};" : "=l"(r) : "f"(lo), "f"(hi));
    return r;
}
__device__ __forceinline__ void unpack2(unsigned long long v, float& lo, float& hi) {
    asm("mov.b64 {%0, %1}, %2;" : "=f"(lo), "=f"(hi) : "l"(v));
}
__device__ __forceinline__ void ffma2(unsigned long long& d,
                                      unsigned long long a, unsigned long long b) {
    asm("fma.rn.f32x2 %0, %1, %2, %0;" : "+l"(d) : "l"(a), "l"(b));
}

__global__ void rnn_first(const float* __restrict__ x0,
                          const float* __restrict__ Wi2h) {
    __shared__ unsigned long long Asd[2][16][34];
    __shared__ float Bs[2][16][68];

    const int tid = threadIdx.x;
    const int tx = tid & 15, ty = tid >> 4;
    const int rowBase = blockIdx.y * 32;
    const int colBase = blockIdx.x * 64;
    const int am = tid >> 3, ak = (tid & 7) * 2;
    const int bk = tid >> 4, bn = (tid & 15) * 4;

    const float* Aptr = &x0[(size_t)(rowBase + am) * INPUT + ak];
    const float* Bptr = &Wi2h[(size_t)bk * HIDDEN + colBase + bn];

    unsigned long long acc[2][2];
    acc[0][0] = acc[0][1] = acc[1][0] = acc[1][1] = 0ull;

    float2 rA = *(const float2*)Aptr;
    float4 rB = *(const float4*)Bptr;

    const int nT = INPUT >> 4;
    for (int tt = 0; tt < nT; ++tt) {
        const int buf = tt & 1;
        Asd[buf][ak][am]     = pack2(rA.x, rA.x);
        Asd[buf][ak + 1][am] = pack2(rA.y, rA.y);
        *(float4*)&Bs[buf][bk][bn] = rB;
        __syncthreads();
        if (tt + 1 < nT) {
            rA = *(const float2*)(Aptr + (tt + 1) * 16);
            rB = *(const float4*)(Bptr + (size_t)(tt + 1) * 16 * HIDDEN);
        }
#pragma unroll
        for (int kk = 0; kk < 16; ++kk) {
            ulonglong2 ap = *(const ulonglong2*)&Asd[buf][kk][2 * ty];
            ulonglong2 bp = *(const ulonglong2*)&Bs[buf][kk][4 * tx];
            ffma2(acc[0][0], ap.x, bp.x);
            ffma2(acc[0][1], ap.x, bp.y);
            ffma2(acc[1][0], ap.y, bp.x);
            ffma2(acc[1][1], ap.y, bp.y);
        }
    }

    float4 bv = *(const float4*)&g_b1[colBase + 4 * tx];
    float o[2][4];
#pragma unroll
    for (int r = 0; r < 2; ++r) {
        unpack2(acc[r][0], o[r][0], o[r][1]);
        unpack2(acc[r][1], o[r][2], o[r][3]);
        o[r][0] += bv.x; o[r][1] += bv.y; o[r][2] += bv.z; o[r][3] += bv.w;
#pragma unroll
        for (int c = 0; c < 4; ++c) o[r][c] = tanhf(o[r][c]);
        *(float4*)&g_H1[rowBase + 2 * ty + r][colBase + 4 * tx] =
            make_float4(o[r][0], o[r][1], o[r][2], o[r][3]);
    }
}

// ---------------------------- prep kernels ---------------------------------
__global__ void prep_weff(const float* __restrict__ Wh2h,
                          const float* __restrict__ Wh2o,
                          const float* __restrict__ Wi2h) {
    int idx = blockIdx.x * blockDim.x + threadIdx.x;
    int k = idx >> 10, j = idx & 1023;
    float s = Wh2h[idx];
    const float* wo = &Wh2o[k * OUTPUT];
#pragma unroll 8
    for (int i = 0; i < OUTPUT; ++i)
        s += wo[i] * Wi2h[i * HIDDEN + j];
    __nv_bfloat16 wh = __float2bfloat16(s);
    g_BT[0][j][k] = wh;
    g_BT[1][j][k] = __float2bfloat16(s - __bfloat162float(wh));
}

__global__ void prep_bo(const float* __restrict__ Wh2o) {
    int idx = blockIdx.x * blockDim.x + threadIdx.x;   // HIDDEN*OUTPUT
    int k = idx >> 7, n = idx & 127;
    float w = Wh2o[k * OUTPUT + n];
    __nv_bfloat16 wh = __float2bfloat16(w);
    g_BTo[0][n][k] = wh;
    g_BTo[1][n][k] = __float2bfloat16(w - __bfloat162float(wh));
}

__global__ void prep_bias(const float* __restrict__ bi2h,
                          const float* __restrict__ bh2h,
                          const float* __restrict__ bh2o,
                          const float* __restrict__ Wi2h) {
    int j = blockIdx.x * blockDim.x + threadIdx.x;
    if (j >= HIDDEN) return;
    float base = bi2h[j] + bh2h[j];
    g_b1[j] = base;
    float s = base;
#pragma unroll 8
    for (int i = 0; i < OUTPUT; ++i)
        s += bh2o[i] * Wi2h[i * HIDDEN + j];
    g_beff[j] = s;
}

__global__ void split_h1() {
    int idx = blockIdx.x * blockDim.x + threadIdx.x;   // 256*1024
    int m = idx >> 10, n = idx & 1023;
    float x = g_H1[m][n];
    __nv_bfloat16 h = __float2bfloat16(x);
    g_Hs[1][0][m][n] = h;
    g_Hs[1][1][m][n] = __float2bfloat16(x - __bfloat162float(h));
}

__global__ void copy_x0(const float* __restrict__ x0, float* __restrict__ out) {
    int i = blockIdx.x * blockDim.x + threadIdx.x;
    if (i < BATCH * OUTPUT) out[i] = x0[i];
}

// ---------------------------- launcher -------------------------------------
extern "C" void kernel_launch(void* const* d_in, const int* in_sizes, int n_in,
                              void* d_out, int out_size) {
    const float* x0   = (const float*)d_in[0];
    const float* Wi2h = (const float*)d_in[1];
    const float* bi2h = (const float*)d_in[2];
    const float* Wh2h = (const float*)d_in[3];
    const float* bh2h = (const float*)d_in[4];
    const float* Wh2o = (const float*)d_in[5];
    const float* bh2o = (const float*)d_in[6];
    float* out = (float*)d_out;

    static bool attrs_set = false;
    cudaFuncSetAttribute(rnn_step_hmma,
                         cudaFuncAttributeMaxDynamicSharedMemorySize,
                         S_TOTAL_E * 2);
    cudaFuncSetAttribute(out_proj_hmma,
                         cudaFuncAttributeMaxDynamicSharedMemorySize,
                         O_TOTAL_E * 2);
    (void)attrs_set;

    prep_weff<<<(HIDDEN * HIDDEN) / 256, 256>>>(Wh2h, Wh2o, Wi2h);
    prep_bo<<<(HIDDEN * OUTPUT) / 256, 256>>>(Wh2o);
    prep_bias<<<(HIDDEN + 255) / 256, 256>>>(bi2h, bh2h, bh2o, Wi2h);
    copy_x0<<<(BATCH * OUTPUT + 255) / 256, 256>>>(x0, out);

    rnn_first<<<dim3(HIDDEN / 64, BATCH / 32), 256>>>(x0, Wi2h);
    split_h1<<<(BATCH * HIDDEN) / 256, 256>>>();

    for (int t = 2; t < TSTEPS; ++t)
        rnn_step_hmma<<<dim3(16, 8), 256, S_TOTAL_E * 2>>>(t);

    out_proj_hmma<<<dim3(OUTPUT / 64, (TSTEPS - 1) * BATCH / 128), 256,
                    O_TOTAL_E * 2>>>(bh2o, out);
}